// round 5
// baseline (speedup 1.0000x reference)
#include <cuda_runtime.h>
#include <math.h>
#include <stdint.h>

#define MAXT  10000
#define BATCH 4096

#define LOG_GAMMA_F  0.019802627296179712f
#define ALPHA_F     (-1.0050335853501441e-05f)
#define INIT_LOGW_D (-1.3943265262)
#define INIT_LOGP_D (-6.907755278982137)
#define EPSF 1e-12f

#define SBLK 40          // scan blocks (40*256 = 10240 >= MAXT)
#define STH  256

#define DCH  32          // detect t-chunk
#define DVEC 4           // batch elems per detect thread
#define DGX  (BATCH / (256 * DVEC))            // 4
#define DGY  ((MAXT + DCH - 1) / DCH)          // 313
#define DTOT (DGX * DGY)

__device__ float  g_csum[SBLK];
__device__ float  g_dsum[SBLK];
__device__ float  g_rsum[SBLK];
__device__ float  g_rinc[MAXT];    // block-local INCLUSIVE prefix of r
__device__ double g_rpre[SBLK];    // cross-block EXCLUSIVE prefix of r-sums
__device__ float2 g_thr[MAXT];     // {Rthr, u2thr} per step
__device__ int    g_death[BATCH];
__device__ int    g_tactive = MAXT;  // first step where death is impossible
__device__ double g_acc;
__device__ unsigned g_cnt;
__device__ unsigned g_bar;         // scanB internal barrier

// ---- parallel double-sum of first B entries of a 40-float smem array ----
__device__ __forceinline__ double par_sum40(const float* vals, int B,
                                            double* wtmp, double* res, int tid) {
    __syncthreads();
    double x = 0.0;
    if (tid < SBLK && tid < B) x = (double)vals[tid];
    if (tid < 64) {
        #pragma unroll
        for (int o = 16; o > 0; o >>= 1) x += __shfl_down_sync(0xffffffffu, x, o);
        if ((tid & 31) == 0) wtmp[tid >> 5] = x;
    }
    __syncthreads();
    if (tid == 0) *res = wtmp[0] + wtmp[1];
    __syncthreads();
    return *res;
}

// ---- block-local inclusive scan (256 threads, fp32) ----
__device__ __forceinline__ float blk_scan_incl(float v, int tid, float* wsm) {
    __syncthreads();
    float x = v;
    #pragma unroll
    for (int o = 1; o < 32; o <<= 1) {
        float y = __shfl_up_sync(0xffffffffu, x, o);
        if ((tid & 31) >= o) x += y;
    }
    int wid = tid >> 5, lid = tid & 31;
    if (lid == 31) wsm[wid] = x;
    __syncthreads();
    if (wid == 0) {
        float w = (lid < 8) ? wsm[lid] : 0.0f;
        #pragma unroll
        for (int o = 1; o < 8; o <<= 1) {
            float y = __shfl_up_sync(0xffffffffu, w, o);
            if (lid >= o) w += y;
        }
        if (lid < 8) wsm[lid] = w;
    }
    __syncthreads();
    float base = (wid == 0) ? 0.0f : wsm[wid - 1];
    return base + x;
}

// ---------------- K1: per-block c sums + all state resets ----------------
__global__ void scanA_kernel(const float* __restrict__ acts) {
    __shared__ float wsm[8];
    int tid = threadIdx.x, bid = blockIdx.x;
    int t = bid * STH + tid;
    float c = 0.0f;
    if (t < MAXT) {
        float f = __expf(__ldg(acts + t));
        c = LOG_GAMMA_F + log1pf(-f);
    }
    float x = c;
    #pragma unroll
    for (int o = 16; o > 0; o >>= 1) x += __shfl_down_sync(0xffffffffu, x, o);
    if ((tid & 31) == 0) wsm[tid >> 5] = x;
    __syncthreads();
    if (tid == 0) {
        float s = 0.0f;
        #pragma unroll
        for (int i = 0; i < 8; i++) s += wsm[i];
        g_csum[bid] = s;
        if (bid == 0) { g_acc = 0.0; g_cnt = 0u; g_bar = 0u; g_tactive = MAXT; }
    }
    if (bid < BATCH / STH) g_death[bid * STH + tid] = MAXT;
}

// ---------------- K2: d/r prefixes, thresholds, rpre (internal 40-block barrier) ----------------
__global__ void __launch_bounds__(STH, 1) scanB_kernel(const float* __restrict__ acts) {
    __shared__ float wsm[8];
    __shared__ float sv[SBLK];
    __shared__ double wtmp[2];
    __shared__ double sres;
    int tid = threadIdx.x, bid = blockIdx.x;
    int t = bid * STH + tid;

    if (tid < SBLK) sv[tid] = g_csum[tid];
    float f = 0.0f, c = 0.0f;
    if (t < MAXT) {
        f = __expf(__ldg(acts + t));
        c = LOG_GAMMA_F + log1pf(-f);
    }
    __syncthreads();
    double cbase = par_sum40(sv, bid, wtmp, &sres, tid);

    float cinc = blk_scan_incl(c, tid, wsm);
    float lwb = (float)(INIT_LOGW_D + cbase) + (cinc - c);   // logw BEFORE step t

    // logw grows to ~196; clamp exp arg (only affects provably-dead region)
    float d = 0.0f, r = 0.0f;
    if (t < MAXT) {
        d = (ALPHA_F * f) * __expf(fminf(lwb, 30.0f));
        r = __expf((lwb + c) * 0.001f);            // exp(new_logw/1000)
    }
    float dinc = blk_scan_incl(d, tid, wsm);
    float rinc = blk_scan_incl(r, tid, wsm);
    if (t < MAXT) g_rinc[t] = rinc;
    if (tid == STH - 1) {
        g_dsum[bid] = dinc;
        g_rsum[bid] = rinc;
        __threadfence();
    }
    __syncthreads();
    // 40-block spin barrier (all CTAs co-resident; g_bar reset by scanA this launch)
    if (tid == 0) {
        atomicAdd(&g_bar, 1u);
        while (*(volatile unsigned*)&g_bar < (unsigned)SBLK) { }
    }
    __syncthreads();

    // cross-block d prefix -> thresholds; cross-block r prefix -> g_rpre
    if (tid < SBLK) sv[tid] = g_dsum[tid];
    double dbase = par_sum40(sv, bid, wtmp, &sres, tid);
    if (tid < SBLK) sv[tid] = g_rsum[tid];
    double rpre = par_sum40(sv, bid, wtmp, &sres, tid);
    if (tid == 0) g_rpre[bid] = rpre;

    float R = 0.0f;
    if (t < MAXT) {
        float lp = (float)(INIT_LOGP_D + dbase) + (dinc - d);  // logp BEFORE step t
        float p = __expf(fmaxf(lp, -87.0f));
        R = p * (1.0f + p * (1.0f + p)) - 1e-12f;              // p/(1-p) - eps
        float U = fmaf(-27.66f, R, 0.99999988f);               // conservative exp lower bound
        g_thr[t] = make_float2(R, U);
    }
    // first inactive step: block-local min, then ONE atomicMin per block
    int bad = (t < MAXT && R < 1e-9f) ? t : 0x7fffffff;
    #pragma unroll
    for (int o = 16; o > 0; o >>= 1) bad = min(bad, __shfl_down_sync(0xffffffffu, bad, o));
    __shared__ int sbad[8];
    if ((tid & 31) == 0) sbad[tid >> 5] = bad;
    __syncthreads();
    if (tid == 0) {
        int m = 0x7fffffff;
        #pragma unroll
        for (int i = 0; i < 8; i++) m = min(m, sbad[i]);
        if (m != 0x7fffffff) atomicMin(&g_tactive, m);
    }
}

// ---------------- K3: detect first deaths + fused finalize ----------------
__global__ void __launch_bounds__(256, 1) detectF_kernel(const float* __restrict__ u1,
                                                         const float* __restrict__ u2,
                                                         float* __restrict__ out) {
    __shared__ float sR[DCH], sU[DCH];
    __shared__ int s_active, s_last;
    int tid = threadIdx.x;
    int t0 = blockIdx.y * DCH;

    if (tid == 0) s_active = (t0 < g_tactive);   // thresholds monotone decreasing
    __syncthreads();

    if (s_active) {
        if (tid < DCH) {
            int t = t0 + tid;
            float2 th = (t < MAXT) ? g_thr[t] : make_float2(0.0f, 2.0f);
            sR[tid] = th.x; sU[tid] = th.y;
        }
        __syncthreads();

        int b0 = blockIdx.x * (256 * DVEC) + tid * DVEC;
        const float* p2 = u2 + (size_t)t0 * BATCH + b0;
        const float* p1 = u1 + (size_t)t0 * BATCH + b0;
        int ft0 = 0x7fffffff, ft1 = 0x7fffffff, ft2 = 0x7fffffff, ft3 = 0x7fffffff;
        #pragma unroll 4
        for (int i = 0; i < DCH; i++) {
            float4 v2 = __ldg((const float4*)(p2 + (size_t)i * BATCH));
            float U = sU[i];
            float mx = fmaxf(fmaxf(v2.x, v2.y), fmaxf(v2.z, v2.w));
            if (mx + EPSF > U) {                    // rare (~3% per component)
                float R = sR[i];
                const float* q1 = p1 + (size_t)i * BATCH;
                #define XR_CHECK(comp, q1off, ftv)                                        \
                    if (comp + EPSF > U) {                                                \
                        float v1 = __ldg(q1 + q1off);                                     \
                        float L1 = logf(v1 + EPSF);                                       \
                        float y = R * L1;                                                 \
                        float ey = 1.0f + y * (1.0f + y * (0.5f + y *                     \
                                   (0.16666667f + y * 0.04166667f)));                     \
                        if (comp + EPSF > ey) ftv = min(ftv, t0 + i);                     \
                    }
                XR_CHECK(v2.x, 0, ft0)
                XR_CHECK(v2.y, 1, ft1)
                XR_CHECK(v2.z, 2, ft2)
                XR_CHECK(v2.w, 3, ft3)
                #undef XR_CHECK
            }
        }
        if (ft0 != 0x7fffffff) atomicMin(&g_death[b0 + 0], ft0);
        if (ft1 != 0x7fffffff) atomicMin(&g_death[b0 + 1], ft1);
        if (ft2 != 0x7fffffff) atomicMin(&g_death[b0 + 2], ft2);
        if (ft3 != 0x7fffffff) atomicMin(&g_death[b0 + 3], ft3);
    }

    // ---- ticket: last block to finish performs the finalize ----
    __syncthreads();
    if (tid == 0) {
        __threadfence();
        unsigned o = atomicAdd(&g_cnt, 1u);
        s_last = (o == (unsigned)(DTOT - 1));
    }
    __syncthreads();
    if (!s_last) return;

    __threadfence();                    // all prior blocks' g_death visible
    __shared__ double rpre[SBLK];
    __shared__ double sh[8];
    if (tid < SBLK) rpre[tid] = g_rpre[tid];
    __syncthreads();

    double acc = 0.0;
    #pragma unroll
    for (int k = 0; k < BATCH / 256; k++) {
        int b = k * 256 + tid;
        int t = g_death[b];
        if (t > MAXT) t = MAXT;
        if (t > 0) {
            int tm = t - 1;
            acc += rpre[tm >> 8] + (double)g_rinc[tm];   // S[t-1]
        }
    }
    #pragma unroll
    for (int o = 16; o > 0; o >>= 1) acc += __shfl_down_sync(0xffffffffu, acc, o);
    if ((tid & 31) == 0) sh[tid >> 5] = acc;
    __syncthreads();
    if (tid == 0) {
        double s = 0.0;
        #pragma unroll
        for (int i = 0; i < 8; i++) s += sh[i];
        out[0] = (float)(s / (double)BATCH);
    }
}

extern "C" void kernel_launch(void* const* d_in, const int* in_sizes, int n_in,
                              void* d_out, int out_size) {
    const float* acts = (const float*)d_in[0];
    const float* u1   = (const float*)d_in[1];
    const float* u2   = (const float*)d_in[2];
    (void)in_sizes; (void)n_in; (void)out_size;

    scanA_kernel<<<SBLK, STH>>>(acts);
    scanB_kernel<<<SBLK, STH>>>(acts);
    dim3 grid(DGX, DGY);
    detectF_kernel<<<grid, 256>>>(u1, u2, (float*)d_out);
}

// round 6
// speedup vs baseline: 1.0205x; 1.0205x over previous
#include <cuda_runtime.h>
#include <math.h>
#include <stdint.h>

#define MAXT  10000
#define BATCH 4096

#define LOG_GAMMA_F  0.019802627296179712f
#define ALPHA_F     (-1.0050335853501441e-05f)
#define INIT_LOGW_D (-1.3943265262)
#define INIT_LOGP_D (-6.907755278982137)
#define EPSF 1e-12f

#define GRID 148
#define BLK  256
#define SBLK 40          // scan chunks (40*256 = 10240 >= MAXT)
#define DCH  32          // detect t-chunk rows
#define DGX  4           // batch slices (4 * 256thr * 4elem = 4096)

__device__ float  g_csum[SBLK];
__device__ float  g_dsum[SBLK];
__device__ float  g_rsum[SBLK];
__device__ float  g_rinc[MAXT];     // block-local INCLUSIVE prefix of r
__device__ double g_rpre[SBLK];     // cross-block EXCLUSIVE prefix of r-sums
__device__ float2 g_thr[MAXT];      // {Rthr, u2thr}
__device__ int    g_death[BATCH];
__device__ int    g_tactive = MAXT;
__device__ unsigned g_cnt0, g_cnt1, g_cnt2, g_done;     // zero-init; reset by finalizer
__device__ volatile unsigned g_flag0, g_flag1, g_flag2; // zero-init; reset by finalizer

// ---- grid-wide spin barrier (all GRID CTAs co-resident by construction) ----
__device__ __forceinline__ void gbar(unsigned* cnt, volatile unsigned* flag, int tid) {
    __syncthreads();
    if (tid == 0) {
        __threadfence();
        if (atomicAdd(cnt, 1u) == GRID - 1) {
            *flag = 1u;
        } else {
            while (*flag == 0u) { }
        }
        __threadfence();
    }
    __syncthreads();
}

// ---- 64-thread double-sum of first B entries of a 40-float smem array ----
__device__ __forceinline__ double par_sum40(const float* vals, int B,
                                            double* wtmp, double* res, int tid) {
    __syncthreads();
    double x = 0.0;
    if (tid < SBLK && tid < B) x = (double)vals[tid];
    if (tid < 64) {
        #pragma unroll
        for (int o = 16; o > 0; o >>= 1) x += __shfl_down_sync(0xffffffffu, x, o);
        if ((tid & 31) == 0) wtmp[tid >> 5] = x;
    }
    __syncthreads();
    if (tid == 0) *res = wtmp[0] + wtmp[1];
    __syncthreads();
    return *res;
}

// ---- block-local inclusive scan (256 threads, fp32) ----
__device__ __forceinline__ float blk_scan_incl(float v, int tid, float* wsm) {
    __syncthreads();
    float x = v;
    #pragma unroll
    for (int o = 1; o < 32; o <<= 1) {
        float y = __shfl_up_sync(0xffffffffu, x, o);
        if ((tid & 31) >= o) x += y;
    }
    int wid = tid >> 5, lid = tid & 31;
    if (lid == 31) wsm[wid] = x;
    __syncthreads();
    if (wid == 0) {
        float w = (lid < 8) ? wsm[lid] : 0.0f;
        #pragma unroll
        for (int o = 1; o < 8; o <<= 1) {
            float y = __shfl_up_sync(0xffffffffu, w, o);
            if (lid >= o) w += y;
        }
        if (lid < 8) wsm[lid] = w;
    }
    __syncthreads();
    float base = (wid == 0) ? 0.0f : wsm[wid - 1];
    return base + x;
}

__global__ void xrisk_kernel(const float* __restrict__ acts,
                             const float* __restrict__ u1,
                             const float* __restrict__ u2,
                             float* __restrict__ out) {
    __shared__ float wsm[8];
    __shared__ float sv[SBLK];
    __shared__ double wtmp[2];
    __shared__ double sres;
    __shared__ float sR[DCH], sU[DCH];
    __shared__ int s_fin;
    __shared__ double sh[8];

    int tid = threadIdx.x, bid = blockIdx.x;
    bool scanb = (bid < SBLK);
    int t = bid * BLK + tid;                 // scan element for scan blocks

    // ---------- Phase 1: per-chunk c sums; death reset ----------
    float f = 0.0f, c = 0.0f;
    if (scanb) {
        if (t < MAXT) {
            f = __expf(__ldg(acts + t));
            c = LOG_GAMMA_F + log1pf(-f);
        }
        float x = c;
        #pragma unroll
        for (int o = 16; o > 0; o >>= 1) x += __shfl_down_sync(0xffffffffu, x, o);
        if ((tid & 31) == 0) wsm[tid >> 5] = x;
        __syncthreads();
        if (tid == 0) {
            float s = 0.0f;
            #pragma unroll
            for (int i = 0; i < 8; i++) s += wsm[i];
            g_csum[bid] = s;
        }
    } else if (bid >= SBLK && bid < SBLK + BATCH / BLK) {
        g_death[(bid - SBLK) * BLK + tid] = MAXT;
    }
    gbar(&g_cnt0, &g_flag0, tid);

    // ---------- Phase 2: d/r block prefixes ----------
    float d = 0.0f, r = 0.0f, dinc = 0.0f;
    if (scanb) {
        if (tid < SBLK) sv[tid] = g_csum[tid];
        double cbase = par_sum40(sv, bid, wtmp, &sres, tid);
        float cinc = blk_scan_incl(c, tid, wsm);
        float lwb = (float)(INIT_LOGW_D + cbase) + (cinc - c);  // logw BEFORE step t
        if (t < MAXT) {
            // logw grows to ~196; clamp exp arg (only the provably-dead region)
            d = (ALPHA_F * f) * __expf(fminf(lwb, 30.0f));
            r = __expf((lwb + c) * 0.001f);     // exp(new_logw/1000)
        }
        dinc = blk_scan_incl(d, tid, wsm);
        float rinc = blk_scan_incl(r, tid, wsm);
        if (t < MAXT) g_rinc[t] = rinc;
        if (tid == BLK - 1) {
            g_dsum[bid] = dinc;
            g_rsum[bid] = rinc;
        }
    }
    gbar(&g_cnt1, &g_flag1, tid);

    // ---------- Phase 3: thresholds + tactive + rpre ----------
    if (scanb) {
        if (tid < SBLK) sv[tid] = g_dsum[tid];
        double dbase = par_sum40(sv, bid, wtmp, &sres, tid);
        if (tid < SBLK) sv[tid] = g_rsum[tid];
        double rpre = par_sum40(sv, bid, wtmp, &sres, tid);
        if (tid == 0) g_rpre[bid] = rpre;

        float R = 0.0f;
        if (t < MAXT) {
            float lp = (float)(INIT_LOGP_D + dbase) + (dinc - d);  // logp BEFORE step t
            float p = __expf(fmaxf(lp, -87.0f));
            R = p * (1.0f + p * (1.0f + p)) - 1e-12f;              // p/(1-p) - eps
            float U = fmaf(-27.66f, R, 0.99999988f);               // conservative bound
            g_thr[t] = make_float2(R, U);
        }
        int bad = (t < MAXT && R < 1e-9f) ? t : 0x7fffffff;
        #pragma unroll
        for (int o = 16; o > 0; o >>= 1) bad = min(bad, __shfl_down_sync(0xffffffffu, bad, o));
        __shared__ int sbad[8];
        if ((tid & 31) == 0) sbad[tid >> 5] = bad;
        __syncthreads();
        if (tid == 0) {
            int m = 0x7fffffff;
            #pragma unroll
            for (int i = 0; i < 8; i++) m = min(m, sbad[i]);
            if (m != 0x7fffffff) atomicMin(&g_tactive, m);
        }
    }
    gbar(&g_cnt2, &g_flag2, tid);

    // ---------- Phase 4: detect (only active chunks generate work) ----------
    {
        int ta = g_tactive;
        int nchunks = (ta + DCH - 1) / DCH;
        int nitems = nchunks * DGX;
        for (int item = bid; item < nitems; item += GRID) {
            int t0 = (item >> 2) * DCH;
            int xs = item & 3;
            int nrow = min(DCH, MAXT - t0);
            __syncthreads();
            if (tid < DCH) {
                int tt = t0 + tid;
                float2 th = (tid < nrow) ? g_thr[tt] : make_float2(0.0f, 2.0f);
                sR[tid] = th.x; sU[tid] = th.y;
            }
            __syncthreads();

            int b0 = xs * 1024 + tid * 4;
            const float* p2 = u2 + (size_t)t0 * BATCH + b0;
            const float* p1 = u1 + (size_t)t0 * BATCH + b0;
            int ft0 = 0x7fffffff, ft1 = 0x7fffffff, ft2 = 0x7fffffff, ft3 = 0x7fffffff;
            #pragma unroll 4
            for (int i = 0; i < DCH; i++) {
                if (i >= nrow) break;
                float4 v2 = __ldg((const float4*)(p2 + (size_t)i * BATCH));
                float U = sU[i];
                float mx = fmaxf(fmaxf(v2.x, v2.y), fmaxf(v2.z, v2.w));
                if (mx + EPSF > U) {                 // rare (~3%/component)
                    float R = sR[i];
                    const float* q1 = p1 + (size_t)i * BATCH;
                    #define XR_CHECK(comp, off, ftv)                                      \
                        if (comp + EPSF > U) {                                            \
                            float v1 = __ldg(q1 + off);                                   \
                            float L1 = logf(v1 + EPSF);                                   \
                            float y = R * L1;                                             \
                            float ey = 1.0f + y * (1.0f + y * (0.5f + y *                 \
                                       (0.16666667f + y * 0.04166667f)));                 \
                            if (comp + EPSF > ey) ftv = min(ftv, t0 + i);                 \
                        }
                    XR_CHECK(v2.x, 0, ft0)
                    XR_CHECK(v2.y, 1, ft1)
                    XR_CHECK(v2.z, 2, ft2)
                    XR_CHECK(v2.w, 3, ft3)
                    #undef XR_CHECK
                }
            }
            if (ft0 != 0x7fffffff) atomicMin(&g_death[b0 + 0], ft0);
            if (ft1 != 0x7fffffff) atomicMin(&g_death[b0 + 1], ft1);
            if (ft2 != 0x7fffffff) atomicMin(&g_death[b0 + 2], ft2);
            if (ft3 != 0x7fffffff) atomicMin(&g_death[b0 + 3], ft3);
        }
    }

    // ---------- Arrive-only ticket: last block finalizes ----------
    __syncthreads();
    if (tid == 0) {
        __threadfence();
        unsigned o = atomicAdd(&g_done, 1u);
        s_fin = (o == GRID - 1);
    }
    __syncthreads();
    if (!s_fin) return;

    __threadfence();
    __shared__ double rpre_s[SBLK];
    if (tid < SBLK) rpre_s[tid] = g_rpre[tid];
    __syncthreads();

    double acc = 0.0;
    #pragma unroll
    for (int k = 0; k < BATCH / BLK; k++) {
        int b = k * BLK + tid;
        int td = g_death[b];
        if (td > MAXT) td = MAXT;
        if (td > 0) {
            int tm = td - 1;
            acc += rpre_s[tm >> 8] + (double)g_rinc[tm];   // S[td-1]
        }
    }
    #pragma unroll
    for (int o = 16; o > 0; o >>= 1) acc += __shfl_down_sync(0xffffffffu, acc, o);
    if ((tid & 31) == 0) sh[tid >> 5] = acc;
    __syncthreads();
    if (tid == 0) {
        double s = 0.0;
        #pragma unroll
        for (int i = 0; i < 8; i++) s += sh[i];
        out[0] = (float)(s / (double)BATCH);
        // reset barrier/launch state for the next graph replay
        g_cnt0 = 0u; g_cnt1 = 0u; g_cnt2 = 0u; g_done = 0u;
        g_flag0 = 0u; g_flag1 = 0u; g_flag2 = 0u;
        g_tactive = MAXT;
    }
}

extern "C" void kernel_launch(void* const* d_in, const int* in_sizes, int n_in,
                              void* d_out, int out_size) {
    const float* acts = (const float*)d_in[0];
    const float* u1   = (const float*)d_in[1];
    const float* u2   = (const float*)d_in[2];
    (void)in_sizes; (void)n_in; (void)out_size;
    xrisk_kernel<<<GRID, BLK>>>(acts, u1, u2, (float*)d_out);
}